// round 10
// baseline (speedup 1.0000x reference)
#include <cuda_runtime.h>
#include <cuda_fp16.h>

// SpatialTransformer: 3D trilinear warp, dense displacement field.
// vol: [B=2, D=160, H=160, W=160, C=2] f32, trf: [B,D,H,W,3] f32 -> out like vol.
//
// R10: FUSED producer-consumer kernel.
//  - E[b][y][x][z] (z-innermost), 8B x-pair entries {v[y][x][z], v[y][x+1][z]},
//    both channels fp16 (x-clip baked in). 65.5 MB intermediate.
//  - Build blocks produce E rows and bump g_done[b*160+y] (10 z-tiles/row).
//  - Main blocks (2 lanes/voxel, lane parity = z-plane, 4 voxels/lane) compute
//    their data-dependent needed y-row range, spin on flags, then gather.
//  - Block order interleaves builds/mains (builds lead by 16 rows) so waits
//    are rare; correctness never depends on order (flags gate everything).
// Reference semantics preserved exactly:
//   l0c = clip(floor(loc),0,159); l1c = clip(l0c+1,0,159)
//   d1  = l1c - loc (floor weight, UNCLIPPED loc); d0 = 1 - d1

#define DIM   160
#define BD    320                // B * D
#define NVOX  (BD * DIM * DIM)   // 8,192,000
#define TZ    16                 // z-tile per build block
#define ZSP   163                // smem z-stride in float2 units (160 + 3 pad)
#define NTHR  320
#define PER_B 8000               // blocks per batch item: 1600 build + 6400 main

// 65.5 MB scratch: x-pair volume, z-innermost (device global, no runtime alloc)
__device__ uint2 g_E[NVOX];
// per-row completion counters (b*160 + y), 10 z-tiles each
__device__ int g_done[BD];

static __device__ __forceinline__ unsigned pack_h2(float a, float b) {
    __half2 h = __floats2half2_rn(a, b);
    return *reinterpret_cast<unsigned*>(&h);
}
static __device__ __forceinline__ unsigned pack_f2(float2 v) {
    return pack_h2(v.x, v.y);
}
static __device__ __forceinline__ float2 h2f(unsigned u) {
    __half2 h = *reinterpret_cast<__half2*>(&u);
    return __half22float2(h);
}

__global__ void reset_kernel() { g_done[threadIdx.x] = 0; }

__global__ __launch_bounds__(NTHR)
void fused_kernel(const float* __restrict__ vol,
                  const float* __restrict__ trf,
                  float* __restrict__ out)
{
    __shared__ float2 sm2[TZ * ZSP];      // build: transpose tile (20.9 KB)
    __shared__ float  s_red[2 * (NTHR / 32)];

    const int bi = blockIdx.x;
    const int b  = bi / PER_B;
    const int r  = bi - b * PER_B;
    const int t  = threadIdx.x;

    // ---- decode interleaved role/coords ----
    // units: u=0..3: 40 builds each (rows 0..15). u=4..39: 40 builds (rows
    // 4u..4u+3) + 160 mains (g=u-4). tail: 4x160 mains (g=36..39).
    bool is_build;
    int row = 0, ztile = 0, g = 0, zloc = 0;
    if (r < 160) {
        is_build = true;
        const int u = r / 40, j = r - u * 40;
        row = 4 * u + j / 10;  ztile = j - (j / 10) * 10;
    } else if (r < 7360) {
        const int q = r - 160;
        const int u = 4 + q / 200;
        const int k = q - (u - 4) * 200;
        if (k < 40) { is_build = true;  row = 4 * u + k / 10; ztile = k - (k / 10) * 10; }
        else        { is_build = false; g = u - 4; zloc = k - 40; }
    } else {
        is_build = false;
        const int q = r - 7360;
        g = 36 + q / 160;  zloc = q - (g - 36) * 160;
    }

    if (is_build) {
        // ================= producer: build E rows (z-innermost x-pairs) ======
        const int by = b * DIM + row;
        const int z0 = ztile * TZ;
        const float4* __restrict__ v4 = (const float4*)vol;

        #pragma unroll
        for (int i = 0; i < (TZ * 80) / NTHR; i++) {       // 4 iters
            const int j  = i * NTHR + t;
            const int x4 = j % 80;
            const int zz = j / 80;
            const float4 v = v4[((b * DIM + z0 + zz) * DIM + row) * 80 + x4];
            float2* s = &sm2[zz * ZSP + x4 * 2];
            s[0] = make_float2(v.x, v.y);
            s[1] = make_float2(v.z, v.w);
        }
        __syncthreads();

        #pragma unroll
        for (int i = 0; i < (TZ * DIM) / NTHR; i++) {      // 8 iters
            const int k  = i * NTHR + t;
            const int zz = k & (TZ - 1);
            const int x  = k >> 4;
            const int xp = min(x + 1, DIM - 1);
            const float2* s0 = &sm2[zz * ZSP];
            uint2 e;
            e.x = pack_f2(s0[x]);
            e.y = pack_f2(s0[xp]);
            g_E[(by * DIM + x) * DIM + (z0 + zz)] = e;
        }
        // release: my stores visible, then bump the row counter
        __threadfence();
        __syncthreads();
        if (t == 0) atomicAdd(&g_done[by], 1);
        return;
    }

    // ================= consumer: warp the volume ============================
    const int s   = t & 1;            // 0 -> z0 plane, 1 -> z1 plane
    const int x   = t >> 1;           // 0..159
    const int yb  = g << 2;           // base y
    const int z   = zloc;
    const int zb  = b * DIM + z;
    const float bOff = b ? 4096000.0f : 0.0f;    // b * 160^3 (exact f32)
    const float maxl = (float)(DIM - 1);
    const float fz = (float)z;
    const float fx = (float)x;

    int   vox[4];
    float tz[4], ty[4], tx[4];
    #pragma unroll
    for (int q = 0; q < 4; q++) {
        vox[q] = (zb * DIM + (yb + q)) * DIM + x;
        tz[q] = trf[vox[q] * 3 + 0];
        ty[q] = trf[vox[q] * 3 + 1];
        tx[q] = trf[vox[q] * 3 + 2];
    }

    float wy0[4], wy1[4], wx0[4], wx1[4], wzs[4];
    int   idx0[4], idx1[4];
    float y0min_t = maxl, y1max_t = 0.0f;
    #pragma unroll
    for (int q = 0; q < 4; q++) {
        const float lz = fz + tz[q];
        const float ly = (float)(yb + q) + ty[q];
        const float lx = fx + tx[q];
        const float z0f = fminf(fmaxf(floorf(lz), 0.0f), maxl);
        const float y0f = fminf(fmaxf(floorf(ly), 0.0f), maxl);
        const float x0f = fminf(fmaxf(floorf(lx), 0.0f), maxl);
        const float z1f = fminf(z0f + 1.0f, maxl);
        const float y1f = fminf(y0f + 1.0f, maxl);
        const float x1f = fminf(x0f + 1.0f, maxl);
        wy0[q] = y1f - ly;  wy1[q] = 1.0f - wy0[q];
        wx0[q] = x1f - lx;  wx1[q] = 1.0f - wx0[q];
        const float wz0 = z1f - lz;
        wzs[q] = s ? (1.0f - wz0) : wz0;
        const float zsf = s ? z1f : z0f;
        const float inner = fmaf(x0f, 160.0f, zsf) + bOff;   // exact: < 2^23
        idx0[q] = (int)fmaf(y0f, 25600.0f, inner);
        idx1[q] = (int)fmaf(y1f, 25600.0f, inner);
        y0min_t = fminf(y0min_t, y0f);
        y1max_t = fmaxf(y1max_t, y1f);
    }

    // block-wide min/max of needed rows
    #pragma unroll
    for (int off = 16; off > 0; off >>= 1) {
        y0min_t = fminf(y0min_t, __shfl_xor_sync(0xffffffffu, y0min_t, off));
        y1max_t = fmaxf(y1max_t, __shfl_xor_sync(0xffffffffu, y1max_t, off));
    }
    const int wid = t >> 5;
    if ((t & 31) == 0) { s_red[wid] = y0min_t; s_red[(NTHR / 32) + wid] = y1max_t; }
    __syncthreads();
    if (t == 0) {
        float mn = s_red[0], mx = s_red[NTHR / 32];
        #pragma unroll
        for (int w = 1; w < NTHR / 32; w++) {
            mn = fminf(mn, s_red[w]);
            mx = fmaxf(mx, s_red[(NTHR / 32) + w]);
        }
        const int r0 = b * DIM + (int)mn;
        const int r1 = b * DIM + (int)mx;
        volatile int* vd = g_done;
        for (int rr = r0; rr <= r1; rr++)
            while (vd[rr] < 10) { }       // spin until row complete
    }
    __syncthreads();       // all threads gated; also orders gathers after spin
    __threadfence();       // acquire: see producer stores

    // 8 independent gathers; lane-pair z-adjacent entries share a line ~7/8.
    uint2 eA[4], eB[4];
    #pragma unroll
    for (int q = 0; q < 4; q++) { eA[q] = g_E[idx0[q]]; eB[q] = g_E[idx1[q]]; }

    #pragma unroll
    for (int q = 0; q < 4; q++) {
        const float w00 = wy0[q] * wx0[q], w01 = wy0[q] * wx1[q];
        const float w10 = wy1[q] * wx0[q], w11 = wy1[q] * wx1[q];
        const float2 c00 = h2f(eA[q].x), c01 = h2f(eA[q].y);   // y0: x0, x1
        const float2 c10 = h2f(eB[q].x), c11 = h2f(eB[q].y);   // y1: x0, x1
        float p0 = w00 * c00.x, p1 = w00 * c00.y;
        p0 = fmaf(w01, c01.x, p0);  p1 = fmaf(w01, c01.y, p1);
        p0 = fmaf(w10, c10.x, p0);  p1 = fmaf(w10, c10.y, p1);
        p0 = fmaf(w11, c11.x, p0);  p1 = fmaf(w11, c11.y, p1);
        const float r0 = wzs[q] * p0;
        const float r1 = wzs[q] * p1;
        // single-shfl combine: each lane exports the channel the peer stores
        const float send = s ? r0 : r1;
        const float recv = __shfl_xor_sync(0xffffffffu, send, 1);
        out[vox[q] * 2 + s] = (s ? r1 : r0) + recv;
    }
}

extern "C" void kernel_launch(void* const* d_in, const int* in_sizes, int n_in,
                              void* d_out, int out_size)
{
    const float* vol = (const float*)d_in[0];
    const float* trf = (const float*)d_in[1];
    float* out = (float*)d_out;

    reset_kernel<<<1, BD>>>();
    fused_kernel<<<2 * PER_B, NTHR>>>(vol, trf, out);
}

// round 11
// speedup vs baseline: 2.9480x; 2.9480x over previous
#include <cuda_runtime.h>
#include <cuda_fp16.h>

// SpatialTransformer: 3D trilinear warp, dense displacement field.
// vol: [B=2, D=160, H=160, W=160, C=2] f32, trf: [B,D,H,W,3] f32 -> out like vol.
//
// R11 = R9 two-kernel scheme + smem-staged trf in the main kernel.
//  - E[b][y][x][z] (z-INNERMOST), 8B entries: x-pair {v[y][x][z], v[y][x+1][z]}
//    both channels fp16 (x-clip baked in). 65.5 MB intermediate.
//  - Main: 2 lanes per voxel (even lane -> z0 plane, odd -> z1), 2x 8B gathers
//    per lane (rows y0, y1); lane-pair z-adjacent entries share a 128B line.
//    4 voxels per lane; planes combined via ONE shfl_xor per voxel.
//    trf staged through smem with coalesced float4 loads (kills ~24 scalar-load
//    wavefronts/warp that were polluting L1tex).
//  - Prologue: float4-load / float2-smem transpose (unchanged from R9).
// Reference semantics preserved exactly:
//   l0c = clip(floor(loc),0,159); l1c = clip(l0c+1,0,159)
//   d1  = l1c - loc (floor weight, UNCLIPPED loc); d0 = 1 - d1

#define DIM   160
#define BD    320                // B * D
#define NVOX  (BD * DIM * DIM)   // 8,192,000
#define TZ    16                 // z-tile in prologue
#define ZSP   163                // smem z-stride in float2 units (160 + 3 pad)

// 65.5 MB scratch: x-pair volume, z-innermost (device global, no runtime alloc)
__device__ uint2 g_E[NVOX];

static __device__ __forceinline__ unsigned pack_h2(float a, float b) {
    __half2 h = __floats2half2_rn(a, b);
    return *reinterpret_cast<unsigned*>(&h);
}
static __device__ __forceinline__ unsigned pack_f2(float2 v) {
    return pack_h2(v.x, v.y);
}
static __device__ __forceinline__ float2 h2f(unsigned u) {
    __half2 h = *reinterpret_cast<__half2*>(&u);
    return __half22float2(h);
}

// ---------------------------------------------------------------------------
// Prologue: build E (z-innermost x-pairs) via smem transpose.
// grid = (320 (b*DIM+y), 10 (z-tiles)), block = 256.
// ---------------------------------------------------------------------------
__global__ __launch_bounds__(256)
void build_E_kernel(const float* __restrict__ vol)
{
    __shared__ float2 sm2[TZ * ZSP];   // 16*163*8 = 20.9 KB

    const int by = blockIdx.x;              // b*DIM + y
    const int b  = (by >= DIM) ? 1 : 0;
    const int y  = by - b * DIM;
    const int z0 = blockIdx.y * TZ;
    const int t  = threadIdx.x;
    const float4* __restrict__ v4 = (const float4*)vol;

    // Load TZ z-planes x 160 x as float4 (2 voxels each), coalesced.
    #pragma unroll
    for (int i = 0; i < (TZ * 80) / 256; i++) {
        const int j  = i * 256 + t;
        const int x4 = j % 80;
        const int zz = j / 80;
        const float4 v = v4[((b * DIM + z0 + zz) * DIM + y) * 80 + x4];
        float2* s = &sm2[zz * ZSP + x4 * 2];
        s[0] = make_float2(v.x, v.y);
        s[1] = make_float2(v.z, v.w);
    }
    __syncthreads();

    // Emit entries; k: zz = k&15, x = k>>4 -> E writes in 128B runs.
    #pragma unroll
    for (int i = 0; i < (TZ * DIM) / 256; i++) {
        const int k  = i * 256 + t;
        const int zz = k & (TZ - 1);
        const int x  = k >> 4;
        const int xp = min(x + 1, DIM - 1);
        const float2* s0 = &sm2[zz * ZSP];
        uint2 e;
        e.x = pack_f2(s0[x]);            // (x  )
        e.y = pack_f2(s0[xp]);           // (x+1)
        g_E[(by * DIM + x) * DIM + (z0 + zz)] = e;
    }
}

// ---------------------------------------------------------------------------
// Main: 2 lanes per voxel (lane parity = z-plane), 4 voxels per lane,
// 2 gathers per lane per voxel (rows y0, y1). trf staged via smem (SoA).
// grid = (320 (b*D+z), 40), block = 320 (160 x-pairs); y = blockIdx.y*4 + q.
// ---------------------------------------------------------------------------
__global__ __launch_bounds__(2 * DIM)
void st_warp_kernel(const float* __restrict__ trf,
                    float* __restrict__ out)
{
    __shared__ float s_t[3 * 640];    // [comp][q*160+x], 7.5 KB

    const int tid = threadIdx.x;
    const int s   = tid & 1;          // 0 -> z0 plane, 1 -> z1 plane
    const int x   = tid >> 1;         // 0..159
    const int yb  = blockIdx.y << 2;  // base y (0,4,...,156)
    const int zb  = blockIdx.x;       // 0..319 = b*D + z
    const int z   = (zb >= DIM) ? (zb - DIM) : zb;
    const float bOff = (zb >= DIM) ? 4096000.0f : 0.0f;  // b * 160^3 (exact f32)
    const float maxl = (float)(DIM - 1);
    const float fz = (float)z;
    const float fx = (float)x;

    // ---- stage block's trf slab: 1920 contiguous floats via float4 ----
    {
        const int base4 = ((zb * DIM + yb) * DIM) * 3 / 4;   // float4 index
        const float4* __restrict__ t4 = (const float4*)trf;
        #pragma unroll
        for (int rnd = 0; rnd < 2; rnd++) {
            const int j = rnd * 320 + tid;
            if (j < 480) {
                const float4 v = t4[base4 + j];
                const int jj = j * 4;
                // scatter 4 floats to SoA: comp = jj%3 pattern cycles
                s_t[(jj % 3) * 640 + (jj / 3)]             = v.x;
                s_t[((jj + 1) % 3) * 640 + ((jj + 1) / 3)] = v.y;
                s_t[((jj + 2) % 3) * 640 + ((jj + 2) / 3)] = v.z;
                s_t[((jj + 3) % 3) * 640 + ((jj + 3) / 3)] = v.w;
            }
        }
    }
    __syncthreads();

    float wy0[4], wy1[4], wx0[4], wx1[4], wzs[4];
    int   vox[4], idx0[4], idx1[4];
    #pragma unroll
    for (int q = 0; q < 4; q++) {
        vox[q] = (zb * DIM + (yb + q)) * DIM + x;
        const int sv = q * DIM + x;
        const float tzq = s_t[sv];            // comp 0
        const float tyq = s_t[640 + sv];      // comp 1
        const float txq = s_t[1280 + sv];     // comp 2

        const float lz = fz + tzq;
        const float ly = (float)(yb + q) + tyq;
        const float lx = fx + txq;
        const float z0f = fminf(fmaxf(floorf(lz), 0.0f), maxl);
        const float y0f = fminf(fmaxf(floorf(ly), 0.0f), maxl);
        const float x0f = fminf(fmaxf(floorf(lx), 0.0f), maxl);
        const float z1f = fminf(z0f + 1.0f, maxl);
        const float y1f = fminf(y0f + 1.0f, maxl);
        const float x1f = fminf(x0f + 1.0f, maxl);
        wy0[q] = y1f - ly;  wy1[q] = 1.0f - wy0[q];
        wx0[q] = x1f - lx;  wx1[q] = 1.0f - wx0[q];
        const float wz0 = z1f - lz;
        wzs[q] = s ? (1.0f - wz0) : wz0;
        const float zsf = s ? z1f : z0f;
        // exact integer arithmetic in f32: values < 2^23
        const float inner = fmaf(x0f, 160.0f, zsf) + bOff;
        idx0[q] = (int)fmaf(y0f, 25600.0f, inner);
        idx1[q] = (int)fmaf(y1f, 25600.0f, inner);
    }

    // 8 independent gathers in flight; lane-pair accesses share a line ~15/16.
    uint2 eA[4], eB[4];
    #pragma unroll
    for (int q = 0; q < 4; q++) { eA[q] = g_E[idx0[q]]; eB[q] = g_E[idx1[q]]; }

    #pragma unroll
    for (int q = 0; q < 4; q++) {
        const float w00 = wy0[q] * wx0[q], w01 = wy0[q] * wx1[q];
        const float w10 = wy1[q] * wx0[q], w11 = wy1[q] * wx1[q];
        const float2 c00 = h2f(eA[q].x), c01 = h2f(eA[q].y);   // y0 row: x0, x1
        const float2 c10 = h2f(eB[q].x), c11 = h2f(eB[q].y);   // y1 row: x0, x1
        float p0 = w00 * c00.x, p1 = w00 * c00.y;
        p0 = fmaf(w01, c01.x, p0);  p1 = fmaf(w01, c01.y, p1);
        p0 = fmaf(w10, c10.x, p0);  p1 = fmaf(w10, c10.y, p1);
        p0 = fmaf(w11, c11.x, p0);  p1 = fmaf(w11, c11.y, p1);
        const float r0 = wzs[q] * p0;
        const float r1 = wzs[q] * p1;
        // single-shfl combine: each lane exports the channel the peer stores
        const float send = s ? r0 : r1;
        const float recv = __shfl_xor_sync(0xffffffffu, send, 1);
        // lane s stores channel s -> warp stores are contiguous 128B runs
        out[vox[q] * 2 + s] = (s ? r1 : r0) + recv;
    }
}

extern "C" void kernel_launch(void* const* d_in, const int* in_sizes, int n_in,
                              void* d_out, int out_size)
{
    const float* vol = (const float*)d_in[0];
    const float* trf = (const float*)d_in[1];
    float* out = (float*)d_out;

    dim3 pgrid(BD, DIM / TZ, 1);      // (b*DIM + y, z-tile)
    build_E_kernel<<<pgrid, 256>>>(vol);

    dim3 mgrid(BD, DIM / 4, 1);       // (b*D + z, y/4)
    st_warp_kernel<<<mgrid, 2 * DIM>>>(trf, out);
}

// round 12
// speedup vs baseline: 3.1512x; 1.0689x over previous
#include <cuda_runtime.h>
#include <cuda_fp16.h>

// SpatialTransformer: 3D trilinear warp, dense displacement field.
// vol: [B=2, D=160, H=160, W=160, C=2] f32, trf: [B,D,H,W,3] f32 -> out like vol.
//
// R12 = R9 + cache-policy hints (E fits in L2 now: 65.5 MB < 126 MB).
//  - E[b][y][x][z] (z-INNERMOST), 8B entries: x-pair {v[y][x][z], v[y][x+1][z]}
//    both channels fp16 (x-clip baked in). 65.5 MB intermediate.
//  - Main: 2 lanes per voxel (even lane -> z0 plane, odd -> z1), 2x 8B gathers
//    per lane (rows y0, y1); lane-pair z-adjacent entries share a 128B line.
//    4 voxels per lane; planes combined via ONE shfl_xor per voxel.
//    trf loads __ldcs / out stores __stcs so streaming data doesn't evict the
//    L2-resident E (prologue leaves it dirty in L2) -> lower gather latency.
//  - Prologue: float4-load / float2-smem transpose (unchanged from R9).
// Reference semantics preserved exactly:
//   l0c = clip(floor(loc),0,159); l1c = clip(l0c+1,0,159)
//   d1  = l1c - loc (floor weight, UNCLIPPED loc); d0 = 1 - d1

#define DIM   160
#define BD    320                // B * D
#define NVOX  (BD * DIM * DIM)   // 8,192,000
#define TZ    16                 // z-tile in prologue
#define ZSP   163                // smem z-stride in float2 units (160 + 3 pad)

// 65.5 MB scratch: x-pair volume, z-innermost (device global, no runtime alloc)
__device__ uint2 g_E[NVOX];

static __device__ __forceinline__ unsigned pack_h2(float a, float b) {
    __half2 h = __floats2half2_rn(a, b);
    return *reinterpret_cast<unsigned*>(&h);
}
static __device__ __forceinline__ unsigned pack_f2(float2 v) {
    return pack_h2(v.x, v.y);
}
static __device__ __forceinline__ float2 h2f(unsigned u) {
    __half2 h = *reinterpret_cast<__half2*>(&u);
    return __half22float2(h);
}

// ---------------------------------------------------------------------------
// Prologue: build E (z-innermost x-pairs) via smem transpose.
// grid = (320 (b*DIM+y), 10 (z-tiles)), block = 256.
// ---------------------------------------------------------------------------
__global__ __launch_bounds__(256)
void build_E_kernel(const float* __restrict__ vol)
{
    __shared__ float2 sm2[TZ * ZSP];   // 16*163*8 = 20.9 KB

    const int by = blockIdx.x;              // b*DIM + y
    const int b  = (by >= DIM) ? 1 : 0;
    const int y  = by - b * DIM;
    const int z0 = blockIdx.y * TZ;
    const int t  = threadIdx.x;
    const float4* __restrict__ v4 = (const float4*)vol;

    // Load TZ z-planes x 160 x as float4 (2 voxels each), coalesced.
    #pragma unroll
    for (int i = 0; i < (TZ * 80) / 256; i++) {
        const int j  = i * 256 + t;
        const int x4 = j % 80;
        const int zz = j / 80;
        const float4 v = v4[((b * DIM + z0 + zz) * DIM + y) * 80 + x4];
        float2* s = &sm2[zz * ZSP + x4 * 2];
        s[0] = make_float2(v.x, v.y);
        s[1] = make_float2(v.z, v.w);
    }
    __syncthreads();

    // Emit entries; k: zz = k&15, x = k>>4 -> E writes in 128B runs.
    #pragma unroll
    for (int i = 0; i < (TZ * DIM) / 256; i++) {
        const int k  = i * 256 + t;
        const int zz = k & (TZ - 1);
        const int x  = k >> 4;
        const int xp = min(x + 1, DIM - 1);
        const float2* s0 = &sm2[zz * ZSP];
        uint2 e;
        e.x = pack_f2(s0[x]);            // (x  )
        e.y = pack_f2(s0[xp]);           // (x+1)
        g_E[(by * DIM + x) * DIM + (z0 + zz)] = e;
    }
}

// ---------------------------------------------------------------------------
// Main: 2 lanes per voxel (lane parity = z-plane), 4 voxels per lane,
// 2 gathers per lane per voxel (rows y0, y1).
// grid = (320 (b*D+z), 40), block = 320 (160 x-pairs); y = blockIdx.y*4 + q.
// ---------------------------------------------------------------------------
__global__ __launch_bounds__(2 * DIM)
void st_warp_kernel(const float* __restrict__ trf,
                    float* __restrict__ out)
{
    const int tid = threadIdx.x;
    const int s   = tid & 1;          // 0 -> z0 plane, 1 -> z1 plane
    const int x   = tid >> 1;         // 0..159
    const int yb  = blockIdx.y << 2;  // base y (0,4,...,156)
    const int zb  = blockIdx.x;       // 0..319 = b*D + z
    const int z   = (zb >= DIM) ? (zb - DIM) : zb;
    const float bOff = (zb >= DIM) ? 4096000.0f : 0.0f;  // b * 160^3 (exact f32)
    const float maxl = (float)(DIM - 1);
    const float fz = (float)z;
    const float fx = (float)x;

    int   vox[4];
    float tz[4], ty[4], tx[4];
    #pragma unroll
    for (int q = 0; q < 4; q++) {
        vox[q] = (zb * DIM + (yb + q)) * DIM + x;
        // streaming (evict-first): don't let trf evict the L2-resident E
        tz[q] = __ldcs(&trf[vox[q] * 3 + 0]);
        ty[q] = __ldcs(&trf[vox[q] * 3 + 1]);
        tx[q] = __ldcs(&trf[vox[q] * 3 + 2]);
    }

    float wy0[4], wy1[4], wx0[4], wx1[4], wzs[4];
    int   idx0[4], idx1[4];
    #pragma unroll
    for (int q = 0; q < 4; q++) {
        const float lz = fz + tz[q];
        const float ly = (float)(yb + q) + ty[q];
        const float lx = fx + tx[q];
        const float z0f = fminf(fmaxf(floorf(lz), 0.0f), maxl);
        const float y0f = fminf(fmaxf(floorf(ly), 0.0f), maxl);
        const float x0f = fminf(fmaxf(floorf(lx), 0.0f), maxl);
        const float z1f = fminf(z0f + 1.0f, maxl);
        const float y1f = fminf(y0f + 1.0f, maxl);
        const float x1f = fminf(x0f + 1.0f, maxl);
        wy0[q] = y1f - ly;  wy1[q] = 1.0f - wy0[q];
        wx0[q] = x1f - lx;  wx1[q] = 1.0f - wx0[q];
        const float wz0 = z1f - lz;
        wzs[q] = s ? (1.0f - wz0) : wz0;
        const float zsf = s ? z1f : z0f;
        // exact integer arithmetic in f32: values < 2^23
        const float inner = fmaf(x0f, 160.0f, zsf) + bOff;
        idx0[q] = (int)fmaf(y0f, 25600.0f, inner);
        idx1[q] = (int)fmaf(y1f, 25600.0f, inner);
    }

    // 8 independent gathers in flight; lane-pair accesses share a line ~7/8.
    uint2 eA[4], eB[4];
    #pragma unroll
    for (int q = 0; q < 4; q++) { eA[q] = g_E[idx0[q]]; eB[q] = g_E[idx1[q]]; }

    #pragma unroll
    for (int q = 0; q < 4; q++) {
        const float w00 = wy0[q] * wx0[q], w01 = wy0[q] * wx1[q];
        const float w10 = wy1[q] * wx0[q], w11 = wy1[q] * wx1[q];
        const float2 c00 = h2f(eA[q].x), c01 = h2f(eA[q].y);   // y0 row: x0, x1
        const float2 c10 = h2f(eB[q].x), c11 = h2f(eB[q].y);   // y1 row: x0, x1
        float p0 = w00 * c00.x, p1 = w00 * c00.y;
        p0 = fmaf(w01, c01.x, p0);  p1 = fmaf(w01, c01.y, p1);
        p0 = fmaf(w10, c10.x, p0);  p1 = fmaf(w10, c10.y, p1);
        p0 = fmaf(w11, c11.x, p0);  p1 = fmaf(w11, c11.y, p1);
        const float r0 = wzs[q] * p0;
        const float r1 = wzs[q] * p1;
        // single-shfl combine: each lane exports the channel the peer stores
        const float send = s ? r0 : r1;
        const float recv = __shfl_xor_sync(0xffffffffu, send, 1);
        // lane s stores channel s -> streaming store (write-once data)
        __stcs(&out[vox[q] * 2 + s], (s ? r1 : r0) + recv);
    }
}

extern "C" void kernel_launch(void* const* d_in, const int* in_sizes, int n_in,
                              void* d_out, int out_size)
{
    const float* vol = (const float*)d_in[0];
    const float* trf = (const float*)d_in[1];
    float* out = (float*)d_out;

    dim3 pgrid(BD, DIM / TZ, 1);      // (b*DIM + y, z-tile)
    build_E_kernel<<<pgrid, 256>>>(vol);

    dim3 mgrid(BD, DIM / 4, 1);       // (b*D + z, y/4)
    st_warp_kernel<<<mgrid, 2 * DIM>>>(trf, out);
}

// round 13
// speedup vs baseline: 3.1533x; 1.0007x over previous
#include <cuda_runtime.h>
#include <cuda_fp16.h>

// SpatialTransformer: 3D trilinear warp, dense displacement field.
// vol: [B=2, D=160, H=160, W=160, C=2] f32, trf: [B,D,H,W,3] f32 -> out like vol.
//
// R13 = R9 scheme + full L2-residency discipline for E:
//  - E[b][y][x][z] (z-INNERMOST), 8B entries: x-pair {v[y][x][z], v[y][x+1][z]}
//    both channels fp16 (x-clip baked in). 65.5 MB intermediate (< L2 126 MB).
//  - ALL streaming traffic is evict-first (__ldcs vol, __ldcs trf, __stcs out)
//    so E is the only L2-allocating data: prologue leaves it dirty-resident,
//    main gathers hit L2 instead of DRAM.
//  - Main: 2 lanes per voxel (even lane -> z0 plane, odd -> z1), 2x 8B gathers
//    per lane (rows y0, y1); lane-pair z-adjacent entries share a 128B line.
//    4 voxels per lane; planes combined via ONE shfl_xor per voxel.
// Reference semantics preserved exactly:
//   l0c = clip(floor(loc),0,159); l1c = clip(l0c+1,0,159)
//   d1  = l1c - loc (floor weight, UNCLIPPED loc); d0 = 1 - d1

#define DIM   160
#define BD    320                // B * D
#define NVOX  (BD * DIM * DIM)   // 8,192,000
#define TZ    16                 // z-tile in prologue
#define ZSP   163                // smem z-stride in float2 units (160 + 3 pad)

// 65.5 MB scratch: x-pair volume, z-innermost (device global, no runtime alloc)
__device__ uint2 g_E[NVOX];

static __device__ __forceinline__ unsigned pack_h2(float a, float b) {
    __half2 h = __floats2half2_rn(a, b);
    return *reinterpret_cast<unsigned*>(&h);
}
static __device__ __forceinline__ unsigned pack_f2(float2 v) {
    return pack_h2(v.x, v.y);
}
static __device__ __forceinline__ float2 h2f(unsigned u) {
    __half2 h = *reinterpret_cast<__half2*>(&u);
    return __half22float2(h);
}

// ---------------------------------------------------------------------------
// Prologue: build E (z-innermost x-pairs) via smem transpose.
// grid = (320 (b*DIM+y), 10 (z-tiles)), block = 256.
// ---------------------------------------------------------------------------
__global__ __launch_bounds__(256)
void build_E_kernel(const float* __restrict__ vol)
{
    __shared__ float2 sm2[TZ * ZSP];   // 16*163*8 = 20.9 KB

    const int by = blockIdx.x;              // b*DIM + y
    const int b  = (by >= DIM) ? 1 : 0;
    const int y  = by - b * DIM;
    const int z0 = blockIdx.y * TZ;
    const int t  = threadIdx.x;
    const float4* __restrict__ v4 = (const float4*)vol;

    // Load TZ z-planes x 160 x as float4 (2 voxels each), coalesced.
    // __ldcs: vol is read exactly once -> keep it out of L2 (preserve E).
    #pragma unroll
    for (int i = 0; i < (TZ * 80) / 256; i++) {
        const int j  = i * 256 + t;
        const int x4 = j % 80;
        const int zz = j / 80;
        const float4 v = __ldcs(&v4[((b * DIM + z0 + zz) * DIM + y) * 80 + x4]);
        float2* s = &sm2[zz * ZSP + x4 * 2];
        s[0] = make_float2(v.x, v.y);
        s[1] = make_float2(v.z, v.w);
    }
    __syncthreads();

    // Emit entries; k: zz = k&15, x = k>>4 -> E writes in 128B runs.
    // Default store policy: E should allocate in L2 and stay dirty-resident.
    #pragma unroll
    for (int i = 0; i < (TZ * DIM) / 256; i++) {
        const int k  = i * 256 + t;
        const int zz = k & (TZ - 1);
        const int x  = k >> 4;
        const int xp = min(x + 1, DIM - 1);
        const float2* s0 = &sm2[zz * ZSP];
        uint2 e;
        e.x = pack_f2(s0[x]);            // (x  )
        e.y = pack_f2(s0[xp]);           // (x+1)
        g_E[(by * DIM + x) * DIM + (z0 + zz)] = e;
    }
}

// ---------------------------------------------------------------------------
// Main: 2 lanes per voxel (lane parity = z-plane), 4 voxels per lane,
// 2 gathers per lane per voxel (rows y0, y1).
// grid = (320 (b*D+z), 40), block = 320 (160 x-pairs); y = blockIdx.y*4 + q.
// ---------------------------------------------------------------------------
__global__ __launch_bounds__(2 * DIM)
void st_warp_kernel(const float* __restrict__ trf,
                    float* __restrict__ out)
{
    const int tid = threadIdx.x;
    const int s   = tid & 1;          // 0 -> z0 plane, 1 -> z1 plane
    const int x   = tid >> 1;         // 0..159
    const int yb  = blockIdx.y << 2;  // base y (0,4,...,156)
    const int zb  = blockIdx.x;       // 0..319 = b*D + z
    const int z   = (zb >= DIM) ? (zb - DIM) : zb;
    const float bOff = (zb >= DIM) ? 4096000.0f : 0.0f;  // b * 160^3 (exact f32)
    const float maxl = (float)(DIM - 1);
    const float fz = (float)z;
    const float fx = (float)x;

    const int voxBase = (zb * DIM + yb) * DIM + x;      // q-stride = DIM

    float tz[4], ty[4], tx[4];
    #pragma unroll
    for (int q = 0; q < 4; q++) {
        const float* tp = &trf[(voxBase + q * DIM) * 3];
        // streaming (evict-first): don't let trf evict the L2-resident E
        tz[q] = __ldcs(tp + 0);
        ty[q] = __ldcs(tp + 1);
        tx[q] = __ldcs(tp + 2);
    }

    float wy0[4], wy1[4], wx0[4], wx1[4], wzs[4];
    int   idx0[4], idx1[4];
    #pragma unroll
    for (int q = 0; q < 4; q++) {
        const float lz = fz + tz[q];
        const float ly = (float)(yb + q) + ty[q];
        const float lx = fx + tx[q];
        const float z0f = fminf(fmaxf(floorf(lz), 0.0f), maxl);
        const float y0f = fminf(fmaxf(floorf(ly), 0.0f), maxl);
        const float x0f = fminf(fmaxf(floorf(lx), 0.0f), maxl);
        const float z1f = fminf(z0f + 1.0f, maxl);
        const float y1f = fminf(y0f + 1.0f, maxl);
        const float x1f = fminf(x0f + 1.0f, maxl);
        wy0[q] = y1f - ly;  wy1[q] = 1.0f - wy0[q];
        wx0[q] = x1f - lx;  wx1[q] = 1.0f - wx0[q];
        const float wz0 = z1f - lz;
        wzs[q] = s ? (1.0f - wz0) : wz0;
        const float zsf = s ? z1f : z0f;
        // exact integer arithmetic in f32: values < 2^23
        const float inner = fmaf(x0f, 160.0f, zsf) + bOff;
        idx0[q] = (int)fmaf(y0f, 25600.0f, inner);
        idx1[q] = (int)fmaf(y1f, 25600.0f, inner);
    }

    // 8 independent gathers in flight; lane-pair accesses share a line ~7/8.
    // Default load policy: E gathers allocate/hit in L2.
    uint2 eA[4], eB[4];
    #pragma unroll
    for (int q = 0; q < 4; q++) { eA[q] = g_E[idx0[q]]; eB[q] = g_E[idx1[q]]; }

    #pragma unroll
    for (int q = 0; q < 4; q++) {
        const float w00 = wy0[q] * wx0[q], w01 = wy0[q] * wx1[q];
        const float w10 = wy1[q] * wx0[q], w11 = wy1[q] * wx1[q];
        const float2 c00 = h2f(eA[q].x), c01 = h2f(eA[q].y);   // y0 row: x0, x1
        const float2 c10 = h2f(eB[q].x), c11 = h2f(eB[q].y);   // y1 row: x0, x1
        float p0 = w00 * c00.x, p1 = w00 * c00.y;
        p0 = fmaf(w01, c01.x, p0);  p1 = fmaf(w01, c01.y, p1);
        p0 = fmaf(w10, c10.x, p0);  p1 = fmaf(w10, c10.y, p1);
        p0 = fmaf(w11, c11.x, p0);  p1 = fmaf(w11, c11.y, p1);
        const float r0 = wzs[q] * p0;
        const float r1 = wzs[q] * p1;
        // single-shfl combine: each lane exports the channel the peer stores
        const float send = s ? r0 : r1;
        const float recv = __shfl_xor_sync(0xffffffffu, send, 1);
        // lane s stores channel s -> streaming store (write-once data)
        __stcs(&out[(voxBase + q * DIM) * 2 + s], (s ? r1 : r0) + recv);
    }
}

extern "C" void kernel_launch(void* const* d_in, const int* in_sizes, int n_in,
                              void* d_out, int out_size)
{
    const float* vol = (const float*)d_in[0];
    const float* trf = (const float*)d_in[1];
    float* out = (float*)d_out;

    dim3 pgrid(BD, DIM / TZ, 1);      // (b*DIM + y, z-tile)
    build_E_kernel<<<pgrid, 256>>>(vol);

    dim3 mgrid(BD, DIM / 4, 1);       // (b*D + z, y/4)
    st_warp_kernel<<<mgrid, 2 * DIM>>>(trf, out);
}

// round 14
// speedup vs baseline: 3.2736x; 1.0382x over previous
#include <cuda_runtime.h>
#include <cuda_fp16.h>

// SpatialTransformer: 3D trilinear warp, dense displacement field.
// vol: [B=2, D=160, H=160, W=160, C=2] f32, trf: [B,D,H,W,3] f32 -> out like vol.
//
// R14 = R9 scheme + Programmatic Dependent Launch overlap:
//  - E[b][y][x][z] (z-INNERMOST), 8B entries: x-pair {v[y][x][z], v[y][x+1][z]}
//    both channels fp16 (x-clip baked in). 65.5 MB intermediate.
//  - Main: 2 lanes per voxel (even lane -> z0 plane, odd -> z1), 2x 8B gathers
//    per lane (rows y0, y1); lane-pair z-adjacent entries share a 128B line.
//    4 voxels per lane; planes combined via ONE shfl_xor per voxel.
//  - Main is launched with ProgrammaticStreamSerialization: its blocks start
//    during the build kernel's drain, prefetch trf + compute weights/indices
//    (independent of E), then cudaGridDependencySynchronize() gates the E
//    gathers on full build completion.
// Reference semantics preserved exactly:
//   l0c = clip(floor(loc),0,159); l1c = clip(l0c+1,0,159)
//   d1  = l1c - loc (floor weight, UNCLIPPED loc); d0 = 1 - d1

#define DIM   160
#define BD    320                // B * D
#define NVOX  (BD * DIM * DIM)   // 8,192,000
#define TZ    16                 // z-tile in prologue
#define ZSP   163                // smem z-stride in float2 units (160 + 3 pad)

// 65.5 MB scratch: x-pair volume, z-innermost (device global, no runtime alloc)
__device__ uint2 g_E[NVOX];

static __device__ __forceinline__ unsigned pack_h2(float a, float b) {
    __half2 h = __floats2half2_rn(a, b);
    return *reinterpret_cast<unsigned*>(&h);
}
static __device__ __forceinline__ unsigned pack_f2(float2 v) {
    return pack_h2(v.x, v.y);
}
static __device__ __forceinline__ float2 h2f(unsigned u) {
    __half2 h = *reinterpret_cast<__half2*>(&u);
    return __half22float2(h);
}

// ---------------------------------------------------------------------------
// Prologue: build E (z-innermost x-pairs) via smem transpose.
// grid = (320 (b*DIM+y), 10 (z-tiles)), block = 256.
// ---------------------------------------------------------------------------
__global__ __launch_bounds__(256)
void build_E_kernel(const float* __restrict__ vol)
{
    __shared__ float2 sm2[TZ * ZSP];   // 16*163*8 = 20.9 KB

    const int by = blockIdx.x;              // b*DIM + y
    const int b  = (by >= DIM) ? 1 : 0;
    const int y  = by - b * DIM;
    const int z0 = blockIdx.y * TZ;
    const int t  = threadIdx.x;
    const float4* __restrict__ v4 = (const float4*)vol;

    // Load TZ z-planes x 160 x as float4 (2 voxels each), coalesced.
    #pragma unroll
    for (int i = 0; i < (TZ * 80) / 256; i++) {
        const int j  = i * 256 + t;
        const int x4 = j % 80;
        const int zz = j / 80;
        const float4 v = v4[((b * DIM + z0 + zz) * DIM + y) * 80 + x4];
        float2* s = &sm2[zz * ZSP + x4 * 2];
        s[0] = make_float2(v.x, v.y);
        s[1] = make_float2(v.z, v.w);
    }
    __syncthreads();

    // Emit entries; k: zz = k&15, x = k>>4 -> E writes in 128B runs.
    #pragma unroll
    for (int i = 0; i < (TZ * DIM) / 256; i++) {
        const int k  = i * 256 + t;
        const int zz = k & (TZ - 1);
        const int x  = k >> 4;
        const int xp = min(x + 1, DIM - 1);
        const float2* s0 = &sm2[zz * ZSP];
        uint2 e;
        e.x = pack_f2(s0[x]);            // (x  )
        e.y = pack_f2(s0[xp]);           // (x+1)
        g_E[(by * DIM + x) * DIM + (z0 + zz)] = e;
    }
}

// ---------------------------------------------------------------------------
// Main: 2 lanes per voxel (lane parity = z-plane), 4 voxels per lane,
// 2 gathers per lane per voxel (rows y0, y1). PDL: trf+weights before the
// grid dependency sync, E gathers after.
// grid = (320 (b*D+z), 40), block = 320 (160 x-pairs); y = blockIdx.y*4 + q.
// ---------------------------------------------------------------------------
__global__ __launch_bounds__(2 * DIM)
void st_warp_kernel(const float* __restrict__ trf,
                    float* __restrict__ out)
{
    const int tid = threadIdx.x;
    const int s   = tid & 1;          // 0 -> z0 plane, 1 -> z1 plane
    const int x   = tid >> 1;         // 0..159
    const int yb  = blockIdx.y << 2;  // base y (0,4,...,156)
    const int zb  = blockIdx.x;       // 0..319 = b*D + z
    const int z   = (zb >= DIM) ? (zb - DIM) : zb;
    const float bOff = (zb >= DIM) ? 4096000.0f : 0.0f;  // b * 160^3 (exact f32)
    const float maxl = (float)(DIM - 1);
    const float fz = (float)z;
    const float fx = (float)x;

    const int voxBase = (zb * DIM + yb) * DIM + x;      // q-stride = DIM

    // ---- phase 1 (independent of E): trf loads + weight/index math ----
    float tz[4], ty[4], tx[4];
    #pragma unroll
    for (int q = 0; q < 4; q++) {
        const float* tp = &trf[(voxBase + q * DIM) * 3];
        tz[q] = tp[0];
        ty[q] = tp[1];
        tx[q] = tp[2];
    }

    float wy0[4], wy1[4], wx0[4], wx1[4], wzs[4];
    int   idx0[4], idx1[4];
    #pragma unroll
    for (int q = 0; q < 4; q++) {
        const float lz = fz + tz[q];
        const float ly = (float)(yb + q) + ty[q];
        const float lx = fx + tx[q];
        const float z0f = fminf(fmaxf(floorf(lz), 0.0f), maxl);
        const float y0f = fminf(fmaxf(floorf(ly), 0.0f), maxl);
        const float x0f = fminf(fmaxf(floorf(lx), 0.0f), maxl);
        const float z1f = fminf(z0f + 1.0f, maxl);
        const float y1f = fminf(y0f + 1.0f, maxl);
        const float x1f = fminf(x0f + 1.0f, maxl);
        wy0[q] = y1f - ly;  wy1[q] = 1.0f - wy0[q];
        wx0[q] = x1f - lx;  wx1[q] = 1.0f - wx0[q];
        const float wz0 = z1f - lz;
        wzs[q] = s ? (1.0f - wz0) : wz0;
        const float zsf = s ? z1f : z0f;
        // exact integer arithmetic in f32: values < 2^23
        const float inner = fmaf(x0f, 160.0f, zsf) + bOff;
        idx0[q] = (int)fmaf(y0f, 25600.0f, inner);
        idx1[q] = (int)fmaf(y1f, 25600.0f, inner);
    }

    // ---- gate: all build_E_kernel stores must be visible ----
    cudaGridDependencySynchronize();

    // ---- phase 2: 8 independent gathers; lane pairs share lines ~7/8 ----
    uint2 eA[4], eB[4];
    #pragma unroll
    for (int q = 0; q < 4; q++) { eA[q] = g_E[idx0[q]]; eB[q] = g_E[idx1[q]]; }

    #pragma unroll
    for (int q = 0; q < 4; q++) {
        const float w00 = wy0[q] * wx0[q], w01 = wy0[q] * wx1[q];
        const float w10 = wy1[q] * wx0[q], w11 = wy1[q] * wx1[q];
        const float2 c00 = h2f(eA[q].x), c01 = h2f(eA[q].y);   // y0 row: x0, x1
        const float2 c10 = h2f(eB[q].x), c11 = h2f(eB[q].y);   // y1 row: x0, x1
        float p0 = w00 * c00.x, p1 = w00 * c00.y;
        p0 = fmaf(w01, c01.x, p0);  p1 = fmaf(w01, c01.y, p1);
        p0 = fmaf(w10, c10.x, p0);  p1 = fmaf(w10, c10.y, p1);
        p0 = fmaf(w11, c11.x, p0);  p1 = fmaf(w11, c11.y, p1);
        const float r0 = wzs[q] * p0;
        const float r1 = wzs[q] * p1;
        // single-shfl combine: each lane exports the channel the peer stores
        const float send = s ? r0 : r1;
        const float recv = __shfl_xor_sync(0xffffffffu, send, 1);
        // lane s stores channel s -> warp stores are contiguous 128B runs
        out[(voxBase + q * DIM) * 2 + s] = (s ? r1 : r0) + recv;
    }
}

extern "C" void kernel_launch(void* const* d_in, const int* in_sizes, int n_in,
                              void* d_out, int out_size)
{
    const float* vol = (const float*)d_in[0];
    const float* trf = (const float*)d_in[1];
    float* out = (float*)d_out;

    // Primary: build E (plain launch)
    {
        cudaLaunchConfig_t cfg = {};
        cfg.gridDim  = dim3(BD, DIM / TZ, 1);
        cfg.blockDim = dim3(256, 1, 1);
        cudaLaunchKernelEx(&cfg, build_E_kernel, vol);
    }
    // Secondary: main warp kernel with programmatic stream serialization —
    // its blocks may start during the build's drain; the in-kernel
    // cudaGridDependencySynchronize() gates E reads on build completion.
    {
        cudaLaunchAttribute attr[1];
        attr[0].id = cudaLaunchAttributeProgrammaticStreamSerialization;
        attr[0].val.programmaticStreamSerializationAllowed = 1;

        cudaLaunchConfig_t cfg = {};
        cfg.gridDim  = dim3(BD, DIM / 4, 1);
        cfg.blockDim = dim3(2 * DIM, 1, 1);
        cfg.attrs    = attr;
        cfg.numAttrs = 1;
        cudaLaunchKernelEx(&cfg, st_warp_kernel, trf, out);
    }
}